// round 15
// baseline (speedup 1.0000x reference)
#include <cuda_runtime.h>
#include <cuda_fp16.h>
#include <cstdint>
#include <cstddef>

// Problem constants
#define B_   4
#define L_   4096
#define D_   2048
#define DF_  8192
#define KCAP 2048              // L * 0.5
#define BK   (B_ * KCAP)       // 8192 selected rows total

// ---------------------------------------------------------------------------
// Device scratch (static globals: allocation-free per harness rules)
// ---------------------------------------------------------------------------
__device__ float  g_scores[B_ * L_];
__device__ int    g_idx[BK];
__device__ __half g_xsel[(size_t)BK * D_];    //  32 MB (fp16)
__device__ __half g_h   [(size_t)BK * DF_];   // 128 MB (fp16)
__device__ __half g_w1t [(size_t)DF_ * D_];   //  32 MB (W1^T: [DF, D] K-major fp16)
__device__ __half g_w2t [(size_t)D_ * DF_];   //  32 MB (W2^T: [D, DF] K-major fp16)

// ---------------------------------------------------------------------------
// Helpers
// ---------------------------------------------------------------------------
__device__ __forceinline__ uint32_t cvta_smem(const void* p) {
    uint32_t a;
    asm("{ .reg .u64 t; cvta.to.shared.u64 t, %1; cvt.u32.u64 %0, t; }"
        : "=r"(a) : "l"(p));
    return a;
}

__device__ __forceinline__ float gelu_tanh(float x) {
    float x3 = x * x * x;
    float t  = tanhf(0.7978845608028654f * (x + 0.044715f * x3));
    return 0.5f * x * (1.0f + t);
}

// fp16 HMMA, fp32 accumulate: 2048 MACs per instruction
__device__ __forceinline__ void mma16816(float* d, const uint32_t* a, const uint32_t* b) {
    asm volatile(
        "mma.sync.aligned.m16n8k16.row.col.f32.f16.f16.f32 "
        "{%0,%1,%2,%3}, {%4,%5,%6,%7}, {%8,%9}, {%0,%1,%2,%3};"
        : "+f"(d[0]), "+f"(d[1]), "+f"(d[2]), "+f"(d[3])
        : "r"(a[0]), "r"(a[1]), "r"(a[2]), "r"(a[3]), "r"(b[0]), "r"(b[1]));
}

// ---------------------------------------------------------------------------
// k_zero: zero d_out (runs AFTER gemm1, BEFORE gemm2 — gemm1 never touches out)
// ---------------------------------------------------------------------------
__global__ void k_zero(float4* p, size_t n4) {
    size_t i = (size_t)blockIdx.x * blockDim.x + threadIdx.x;
    size_t stride = (size_t)gridDim.x * blockDim.x;
    float4 z = make_float4(0.f, 0.f, 0.f, 0.f);
    for (; i < n4; i += stride) p[i] = z;
}

// ---------------------------------------------------------------------------
// k_router: router scores (exact fp32) — one warp per token
// ---------------------------------------------------------------------------
__global__ void k_router(const float* __restrict__ x, const float* __restrict__ wr,
                         const float* __restrict__ br) {
    int gw   = (blockIdx.x * blockDim.x + threadIdx.x) >> 5;
    int lane = threadIdx.x & 31;
    if (gw >= B_ * L_) return;
    const float4* row = (const float4*)(x + (size_t)gw * D_);
    const float4* w   = (const float4*)wr;
    float acc = 0.f;
    #pragma unroll 4
    for (int i = lane; i < D_ / 4; i += 32) {
        float4 a = row[i], b = w[i];
        acc += a.x * b.x + a.y * b.y + a.z * b.z + a.w * b.w;
    }
    #pragma unroll
    for (int o = 16; o; o >>= 1) acc += __shfl_xor_sync(0xffffffff, acc, o);
    if (lane == 0) g_scores[gw] = acc + br[0];
}

// ---------------------------------------------------------------------------
// k_topksel: FUSED per-batch threshold (bitonic sort) + compact index build.
// ---------------------------------------------------------------------------
__global__ void k_topksel() {
    __shared__ float s[L_];
    __shared__ int   cnt;
    int b = blockIdx.x, tid = threadIdx.x;
    for (int i = tid; i < L_; i += blockDim.x) s[i] = g_scores[b * L_ + i];
    __syncthreads();
    for (int size = 2; size <= L_; size <<= 1) {
        for (int stride = size >> 1; stride > 0; stride >>= 1) {
            for (int t = tid; t < L_; t += blockDim.x) {
                int p = t ^ stride;
                if (p > t) {
                    bool up = ((t & size) == 0);
                    float a = s[t], c = s[p];
                    if (up ? (a > c) : (a < c)) { s[t] = c; s[p] = a; }
                }
            }
            __syncthreads();
        }
    }
    float thr = s[L_ - KCAP];
    if (tid == 0) cnt = 0;
    __syncthreads();
    for (int i = tid; i < L_; i += blockDim.x) {
        if (g_scores[b * L_ + i] > thr) {
            int p = atomicAdd(&cnt, 1);
            g_idx[b * KCAP + p] = i;
        }
    }
    __syncthreads();
    for (int i = tid; i < L_; i += blockDim.x) {
        if (g_scores[b * L_ + i] == thr) {
            int p = atomicAdd(&cnt, 1);
            if (p < KCAP) g_idx[b * KCAP + p] = i;
        }
    }
}

// ---------------------------------------------------------------------------
// k_prep: FUSED gather(->fp16) + both weight transposes (->fp16 K-major).
// ---------------------------------------------------------------------------
#define NB_T1 ((DF_ / 32) * (D_ / 32))   // 16384
#define NB_T2 ((D_ / 32) * (DF_ / 32))   // 16384
#define NB_PREP (BK + NB_T1 + NB_T2)     // 40960

__global__ void k_prep(const float* __restrict__ x,
                       const float* __restrict__ w1,
                       const float* __restrict__ w2) {
    int blk = blockIdx.x;
    if (blk < BK) {
        int r   = blk;
        int b   = r >> 11;
        int tok = g_idx[r];
        const float4* src = (const float4*)(x + ((size_t)(b * L_ + tok)) * D_);
        __half2*      dst = (__half2*)(g_xsel + (size_t)r * D_);
        for (int i = threadIdx.x; i < D_ / 4; i += blockDim.x) {
            float4 v = src[i];
            dst[2 * i]     = __floats2half2_rn(v.x, v.y);
            dst[2 * i + 1] = __floats2half2_rn(v.z, v.w);
        }
        return;
    }
    __shared__ float t[32][33];
    const float* src; __half* dst; int R, C, bx, by;
    if (blk < BK + NB_T1) {
        int q = blk - BK;
        src = w1; dst = g_w1t; R = D_; C = DF_;
        bx = q % (DF_ / 32); by = q / (DF_ / 32);
    } else {
        int q = blk - BK - NB_T1;
        src = w2; dst = g_w2t; R = DF_; C = D_;
        bx = q % (D_ / 32); by = q / (D_ / 32);
    }
    int tx = threadIdx.x & 31, ty = threadIdx.x >> 5;   // 32 x 8
    int c0 = bx * 32, r0 = by * 32;
    for (int j = ty; j < 32; j += 8)
        t[j][tx] = src[(size_t)(r0 + j) * C + c0 + tx];
    __syncthreads();
    for (int j = ty; j < 32; j += 8)
        dst[(size_t)(c0 + j) * R + r0 + tx] = __float2half_rn(t[tx][j]);
}

// ---------------------------------------------------------------------------
// k_gemm: fp16 mma.sync GEMM  C[M,N] = A[M,K] * Bt[N,K]^T  (+bias epilogue)
//   mode 0: A=g_xsel, Bt=g_w1t, epilogue gelu -> g_h (fp16)
//   mode 1: A=g_h,    Bt=g_w2t, epilogue bias -> scatter fp32 to out via g_idx
// CTA 128x128, TK=64 halfs, 256 threads, 8 warps (2 M x 4 N), warp tile 64x32.
// acc 64 regs/thread (~110 total) -> 2 CTAs/SM -> 16 warps/SM = 4/SMSP,
// double the latency hiding of the 128-thread config (tensor was 56.7% busy).
// 3-stage cp.async ring, one __syncthreads per k-tile, 144B rows conflict-free.
// ---------------------------------------------------------------------------
#define TKH 64                       // k per tile (halfs)
#define SROWH 72                     // halfs per SMEM row (64 data + 8 pad = 144B)
#define A_BYTES (128 * SROWH * 2)    // 18432
#define STAGE_BYTES (2 * A_BYTES)    // 36864 (A then B)
#define NSTAGE 3
#define SM_TOTAL (NSTAGE * STAGE_BYTES)  // 110592

__device__ __forceinline__ void prefetch_stage(
    uint32_t sb, int stage, const __half* __restrict__ A, const __half* __restrict__ Bt,
    size_t rowA0, size_t rowB0, int Ktot, int k0, int tid)
{
    uint32_t base = sb + stage * STAGE_BYTES;
    #pragma unroll
    for (int j = 0; j < 4; j++) {                     // 256 thr: 4 iters = 128 rows
        int c = j * 256 + tid;
        int r = c >> 3, q = c & 7;                    // 8 x 16B chunks per 128B row
        const __half* ga = A  + (rowA0 + (size_t)r) * (size_t)Ktot + k0 + q * 8;
        const __half* gb = Bt + (rowB0 + (size_t)r) * (size_t)Ktot + k0 + q * 8;
        uint32_t sa  = base + (uint32_t)(r * 144 + q * 16);
        uint32_t sbb = sa + A_BYTES;
        asm volatile("cp.async.cg.shared.global [%0], [%1], 16;" :: "r"(sa),  "l"(ga) : "memory");
        asm volatile("cp.async.cg.shared.global [%0], [%1], 16;" :: "r"(sbb), "l"(gb) : "memory");
    }
}

__global__ __launch_bounds__(256, 2) void k_gemm(
    const float* __restrict__ bias, float* __restrict__ out,
    int Ktot, int Ntot, int mode)
{
    extern __shared__ char smem[];
    uint32_t sb = cvta_smem(smem);
    int tid  = threadIdx.x;
    int wid  = tid >> 5;
    int lane = tid & 31;
    int wm   = wid & 1;                       // warp M index (0/1), 64 rows
    int wn   = wid >> 1;                      // warp N index (0..3), 32 cols

    const __half* A  = (mode == 0) ? g_xsel : g_h;
    const __half* Bt = (mode == 0) ? g_w1t  : g_w2t;

    const size_t rowA0 = (size_t)blockIdx.y * 128;
    const size_t colB0 = (size_t)blockIdx.x * 128;
    const int NS = Ktot / TKH;

    float acc[4][4][4];
    #pragma unroll
    for (int mi = 0; mi < 4; mi++)
        #pragma unroll
        for (int ni = 0; ni < 4; ni++)
            #pragma unroll
            for (int j = 0; j < 4; j++) acc[mi][ni][j] = 0.f;

    // prologue: stages 0, 1 in flight
    prefetch_stage(sb, 0, A, Bt, rowA0, colB0, Ktot, 0, tid);
    asm volatile("cp.async.commit_group;" ::: "memory");
    prefetch_stage(sb, 1, A, Bt, rowA0, colB0, Ktot, TKH, tid);
    asm volatile("cp.async.commit_group;" ::: "memory");

    const int lr = lane >> 2;   // 0..7
    const int lc = lane & 3;    // 0..3

    int buf = 0;                // = s % 3
    for (int s = 0; s < NS; s++) {
        asm volatile("cp.async.wait_group 1;" ::: "memory");
        __syncthreads();        // stage s ready; buffer (s+2)%3 free since iter s-1

        if (s + 2 < NS) {
            int nbuf = buf + 2; if (nbuf >= NSTAGE) nbuf -= NSTAGE;
            prefetch_stage(sb, nbuf, A, Bt, rowA0, colB0, Ktot, (s + 2) * TKH, tid);
        }
        asm volatile("cp.async.commit_group;" ::: "memory");

        const __half* sA = (const __half*)(smem + buf * STAGE_BYTES);
        const __half* sB = (const __half*)(smem + buf * STAGE_BYTES + A_BYTES);

        #pragma unroll
        for (int ks = 0; ks < 4; ks++) {            // 4 x k16 = TKH
            int kb = ks * 16;                       // half index within row
            uint32_t afr[4][4];
            uint32_t bfr[4][2];
            #pragma unroll
            for (int mi = 0; mi < 4; mi++) {
                int r = wm * 64 + mi * 16 + lr;
                int c = kb + 2 * lc;
                afr[mi][0] = *(const uint32_t*)(sA + r * SROWH + c);
                afr[mi][1] = *(const uint32_t*)(sA + (r + 8) * SROWH + c);
                afr[mi][2] = *(const uint32_t*)(sA + r * SROWH + c + 8);
                afr[mi][3] = *(const uint32_t*)(sA + (r + 8) * SROWH + c + 8);
            }
            #pragma unroll
            for (int ni = 0; ni < 4; ni++) {
                int n = wn * 32 + ni * 8 + lr;
                int c = kb + 2 * lc;
                bfr[ni][0] = *(const uint32_t*)(sB + n * SROWH + c);
                bfr[ni][1] = *(const uint32_t*)(sB + n * SROWH + c + 8);
            }
            #pragma unroll
            for (int mi = 0; mi < 4; mi++)
                #pragma unroll
                for (int ni = 0; ni < 4; ni++)
                    mma16816(acc[mi][ni], afr[mi], bfr[ni]);
        }

        buf++; if (buf >= NSTAGE) buf -= NSTAGE;
    }

    // ------------------------- epilogue -------------------------
    // accum layout m16n8: c0/c1 at (row lr, col 2*lc / 2*lc+1), c2/c3 at row lr+8
    #pragma unroll
    for (int mi = 0; mi < 4; mi++) {
        size_t m0 = rowA0 + (size_t)(wm * 64 + mi * 16 + lr);
        size_t m1 = m0 + 8;
        if (mode == 0) {
            __half* row0 = g_h + m0 * (size_t)Ntot;
            __half* row1 = g_h + m1 * (size_t)Ntot;
            #pragma unroll
            for (int ni = 0; ni < 4; ni++) {
                size_t col = colB0 + wn * 32 + ni * 8 + lc * 2;
                float b0 = bias[col], b1 = bias[col + 1];
                *(__half2*)(row0 + col) = __floats2half2_rn(
                    gelu_tanh(acc[mi][ni][0] + b0), gelu_tanh(acc[mi][ni][1] + b1));
                *(__half2*)(row1 + col) = __floats2half2_rn(
                    gelu_tanh(acc[mi][ni][2] + b0), gelu_tanh(acc[mi][ni][3] + b1));
            }
        } else {
            int tok0 = g_idx[m0], tok1 = g_idx[m1];
            int b0i = (int)(m0 >> 11), b1i = (int)(m1 >> 11);
            float* row0 = out + ((size_t)(b0i * L_ + tok0)) * D_;
            float* row1 = out + ((size_t)(b1i * L_ + tok1)) * D_;
            #pragma unroll
            for (int ni = 0; ni < 4; ni++) {
                size_t col = colB0 + wn * 32 + ni * 8 + lc * 2;
                float b0 = bias[col], b1 = bias[col + 1];
                float2 v0, v1;
                v0.x = acc[mi][ni][0] + b0;
                v0.y = acc[mi][ni][1] + b1;
                v1.x = acc[mi][ni][2] + b0;
                v1.y = acc[mi][ni][3] + b1;
                *(float2*)(row0 + col) = v0;
                *(float2*)(row1 + col) = v1;
            }
        }
    }
}

// ---------------------------------------------------------------------------
// Host entry.
// Launch order: router(0) topksel(1) prep(2) GEMM1(3=profiled) zero(4) gemm2(5)
// ---------------------------------------------------------------------------
extern "C" void kernel_launch(void* const* d_in, const int* in_sizes, int n_in,
                              void* d_out, int out_size) {
    (void)in_sizes; (void)n_in;
    const float* x  = (const float*)d_in[0];
    const float* wr = (const float*)d_in[1];
    const float* br = (const float*)d_in[2];
    const float* w1 = (const float*)d_in[3];
    const float* b1 = (const float*)d_in[4];
    const float* w2 = (const float*)d_in[5];
    const float* b2 = (const float*)d_in[6];
    float* out = (float*)d_out;

    static int smem_set = 0;
    if (!smem_set) {
        cudaFuncSetAttribute(k_gemm, cudaFuncAttributeMaxDynamicSharedMemorySize, SM_TOTAL);
        smem_set = 1;
    }

    // 0) router scores (fp32 exact)
    k_router<<<(B_ * L_ * 32) / 256, 256>>>(x, wr, br);

    // 1) threshold + index build (fused)
    k_topksel<<<B_, 1024>>>();

    // 2) gather -> fp16  +  both weight transposes -> fp16 K-major (one launch)
    k_prep<<<NB_PREP, 256>>>(x, w1, w2);

    // 3) GEMM1 (profiled slot)
    k_gemm<<<dim3(DF_ / 128, BK / 128), 256, SM_TOTAL>>>(b1, out, D_,  DF_, 0);

    // 4) zero output (gemm1 never touches out; completes before gemm2 scatter)
    k_zero<<<2048, 256>>>((float4*)out, (size_t)out_size / 4);

    // 5) GEMM2 (scatter epilogue)
    k_gemm<<<dim3(D_ / 128, BK / 128), 256, SM_TOTAL>>>(b2, out, DF_, D_, 1);
}

// round 16
// speedup vs baseline: 1.0473x; 1.0473x over previous
#include <cuda_runtime.h>
#include <cuda_fp16.h>
#include <cstdint>
#include <cstddef>

// Problem constants
#define B_   4
#define L_   4096
#define D_   2048
#define DF_  8192
#define KCAP 2048              // L * 0.5
#define BK   (B_ * KCAP)       // 8192 selected rows total

// ---------------------------------------------------------------------------
// Device scratch (static globals: allocation-free per harness rules)
// ---------------------------------------------------------------------------
__device__ float  g_scores[B_ * L_];
__device__ int    g_idx[BK];
__device__ __half g_xsel[(size_t)BK * D_];    //  32 MB (fp16)
__device__ __half g_h   [(size_t)BK * DF_];   // 128 MB (fp16)
__device__ __half g_w1t [(size_t)DF_ * D_];   //  32 MB (W1^T: [DF, D] K-major fp16)
__device__ __half g_w2t [(size_t)D_ * DF_];   //  32 MB (W2^T: [D, DF] K-major fp16)

// ---------------------------------------------------------------------------
// Helpers
// ---------------------------------------------------------------------------
__device__ __forceinline__ uint32_t cvta_smem(const void* p) {
    uint32_t a;
    asm("{ .reg .u64 t; cvta.to.shared.u64 t, %1; cvt.u32.u64 %0, t; }"
        : "=r"(a) : "l"(p));
    return a;
}

// Hardware tanh (MUFU-class, ~1e-5 rel err) — guaranteed fast regardless of
// compiler flags. gelu becomes ~6 ops + 1 SFU op instead of a tanhf software
// expansion; the GEMM1 epilogue (128 gelu/thread) was a tensor-idle tail.
__device__ __forceinline__ float tanh_fast(float x) {
    float y;
    asm("tanh.approx.f32 %0, %1;" : "=f"(y) : "f"(x));
    return y;
}

__device__ __forceinline__ float gelu_tanh(float x) {
    float x3 = x * x * x;
    float t  = tanh_fast(0.7978845608028654f * (x + 0.044715f * x3));
    return 0.5f * x * (1.0f + t);
}

// fp16 HMMA, fp32 accumulate: 2048 MACs per instruction
__device__ __forceinline__ void mma16816(float* d, const uint32_t* a, const uint32_t* b) {
    asm volatile(
        "mma.sync.aligned.m16n8k16.row.col.f32.f16.f16.f32 "
        "{%0,%1,%2,%3}, {%4,%5,%6,%7}, {%8,%9}, {%0,%1,%2,%3};"
        : "+f"(d[0]), "+f"(d[1]), "+f"(d[2]), "+f"(d[3])
        : "r"(a[0]), "r"(a[1]), "r"(a[2]), "r"(a[3]), "r"(b[0]), "r"(b[1]));
}

// ---------------------------------------------------------------------------
// k_zero: zero d_out (runs AFTER gemm1, BEFORE gemm2 — gemm1 never touches out)
// ---------------------------------------------------------------------------
__global__ void k_zero(float4* p, size_t n4) {
    size_t i = (size_t)blockIdx.x * blockDim.x + threadIdx.x;
    size_t stride = (size_t)gridDim.x * blockDim.x;
    float4 z = make_float4(0.f, 0.f, 0.f, 0.f);
    for (; i < n4; i += stride) p[i] = z;
}

// ---------------------------------------------------------------------------
// k_router: router scores (exact fp32) — one warp per token
// ---------------------------------------------------------------------------
__global__ void k_router(const float* __restrict__ x, const float* __restrict__ wr,
                         const float* __restrict__ br) {
    int gw   = (blockIdx.x * blockDim.x + threadIdx.x) >> 5;
    int lane = threadIdx.x & 31;
    if (gw >= B_ * L_) return;
    const float4* row = (const float4*)(x + (size_t)gw * D_);
    const float4* w   = (const float4*)wr;
    float acc = 0.f;
    #pragma unroll 4
    for (int i = lane; i < D_ / 4; i += 32) {
        float4 a = row[i], b = w[i];
        acc += a.x * b.x + a.y * b.y + a.z * b.z + a.w * b.w;
    }
    #pragma unroll
    for (int o = 16; o; o >>= 1) acc += __shfl_xor_sync(0xffffffff, acc, o);
    if (lane == 0) g_scores[gw] = acc + br[0];
}

// ---------------------------------------------------------------------------
// k_topksel: FUSED per-batch threshold (bitonic sort) + compact index build.
// ---------------------------------------------------------------------------
__global__ void k_topksel() {
    __shared__ float s[L_];
    __shared__ int   cnt;
    int b = blockIdx.x, tid = threadIdx.x;
    for (int i = tid; i < L_; i += blockDim.x) s[i] = g_scores[b * L_ + i];
    __syncthreads();
    for (int size = 2; size <= L_; size <<= 1) {
        for (int stride = size >> 1; stride > 0; stride >>= 1) {
            for (int t = tid; t < L_; t += blockDim.x) {
                int p = t ^ stride;
                if (p > t) {
                    bool up = ((t & size) == 0);
                    float a = s[t], c = s[p];
                    if (up ? (a > c) : (a < c)) { s[t] = c; s[p] = a; }
                }
            }
            __syncthreads();
        }
    }
    float thr = s[L_ - KCAP];
    if (tid == 0) cnt = 0;
    __syncthreads();
    for (int i = tid; i < L_; i += blockDim.x) {
        if (g_scores[b * L_ + i] > thr) {
            int p = atomicAdd(&cnt, 1);
            g_idx[b * KCAP + p] = i;
        }
    }
    __syncthreads();
    for (int i = tid; i < L_; i += blockDim.x) {
        if (g_scores[b * L_ + i] == thr) {
            int p = atomicAdd(&cnt, 1);
            if (p < KCAP) g_idx[b * KCAP + p] = i;
        }
    }
}

// ---------------------------------------------------------------------------
// k_prep: FUSED gather(->fp16) + both weight transposes (->fp16 K-major).
// ---------------------------------------------------------------------------
#define NB_T1 ((DF_ / 32) * (D_ / 32))   // 16384
#define NB_T2 ((D_ / 32) * (DF_ / 32))   // 16384
#define NB_PREP (BK + NB_T1 + NB_T2)     // 40960

__global__ void k_prep(const float* __restrict__ x,
                       const float* __restrict__ w1,
                       const float* __restrict__ w2) {
    int blk = blockIdx.x;
    if (blk < BK) {
        int r   = blk;
        int b   = r >> 11;
        int tok = g_idx[r];
        const float4* src = (const float4*)(x + ((size_t)(b * L_ + tok)) * D_);
        __half2*      dst = (__half2*)(g_xsel + (size_t)r * D_);
        for (int i = threadIdx.x; i < D_ / 4; i += blockDim.x) {
            float4 v = src[i];
            dst[2 * i]     = __floats2half2_rn(v.x, v.y);
            dst[2 * i + 1] = __floats2half2_rn(v.z, v.w);
        }
        return;
    }
    __shared__ float t[32][33];
    const float* src; __half* dst; int R, C, bx, by;
    if (blk < BK + NB_T1) {
        int q = blk - BK;
        src = w1; dst = g_w1t; R = D_; C = DF_;
        bx = q % (DF_ / 32); by = q / (DF_ / 32);
    } else {
        int q = blk - BK - NB_T1;
        src = w2; dst = g_w2t; R = DF_; C = D_;
        bx = q % (D_ / 32); by = q / (D_ / 32);
    }
    int tx = threadIdx.x & 31, ty = threadIdx.x >> 5;   // 32 x 8
    int c0 = bx * 32, r0 = by * 32;
    for (int j = ty; j < 32; j += 8)
        t[j][tx] = src[(size_t)(r0 + j) * C + c0 + tx];
    __syncthreads();
    for (int j = ty; j < 32; j += 8)
        dst[(size_t)(c0 + j) * R + r0 + tx] = __float2half_rn(t[tx][j]);
}

// ---------------------------------------------------------------------------
// k_gemm: fp16 mma.sync GEMM  C[M,N] = A[M,K] * Bt[N,K]^T  (+bias epilogue)
//   mode 0: A=g_xsel, Bt=g_w1t, epilogue gelu -> g_h (fp16)
//   mode 1: A=g_h,    Bt=g_w2t, epilogue bias -> scatter fp32 to out via g_idx
// REVERTED to the best-measured Round-13 config (1738us): CTA 128x128,
// TK=64 halfs, 128 threads, 4 warps (2x2), warp tile 64x64, 3-stage
// cp.async ring, one __syncthreads per k-tile, 144B rows conflict-free.
// Only change vs R13: gelu uses tanh.approx (epilogue was a tensor-idle tail).
// ---------------------------------------------------------------------------
#define TKH 64                       // k per tile (halfs)
#define SROWH 72                     // halfs per SMEM row (64 data + 8 pad = 144B)
#define A_BYTES (128 * SROWH * 2)    // 18432
#define STAGE_BYTES (2 * A_BYTES)    // 36864 (A then B)
#define NSTAGE 3
#define SM_TOTAL (NSTAGE * STAGE_BYTES)  // 110592

__device__ __forceinline__ void prefetch_stage(
    uint32_t sb, int stage, const __half* __restrict__ A, const __half* __restrict__ Bt,
    size_t rowA0, size_t rowB0, int Ktot, int k0, int tid)
{
    uint32_t base = sb + stage * STAGE_BYTES;
    #pragma unroll
    for (int j = 0; j < 8; j++) {
        int c = j * 128 + tid;
        int r = c >> 3, q = c & 7;                    // 8 x 16B chunks per 128B row
        const __half* ga = A  + (rowA0 + (size_t)r) * (size_t)Ktot + k0 + q * 8;
        const __half* gb = Bt + (rowB0 + (size_t)r) * (size_t)Ktot + k0 + q * 8;
        uint32_t sa  = base + (uint32_t)(r * 144 + q * 16);
        uint32_t sbb = sa + A_BYTES;
        asm volatile("cp.async.cg.shared.global [%0], [%1], 16;" :: "r"(sa),  "l"(ga) : "memory");
        asm volatile("cp.async.cg.shared.global [%0], [%1], 16;" :: "r"(sbb), "l"(gb) : "memory");
    }
}

__global__ __launch_bounds__(128) void k_gemm(
    const float* __restrict__ bias, float* __restrict__ out,
    int Ktot, int Ntot, int mode)
{
    extern __shared__ char smem[];
    uint32_t sb = cvta_smem(smem);
    int tid  = threadIdx.x;
    int wid  = tid >> 5;
    int lane = tid & 31;
    int wm   = wid & 1;                       // warp M index (0/1)
    int wn   = wid >> 1;                      // warp N index (0/1)

    const __half* A  = (mode == 0) ? g_xsel : g_h;
    const __half* Bt = (mode == 0) ? g_w1t  : g_w2t;

    const size_t rowA0 = (size_t)blockIdx.y * 128;
    const size_t colB0 = (size_t)blockIdx.x * 128;
    const int NS = Ktot / TKH;

    float acc[4][8][4];
    #pragma unroll
    for (int mi = 0; mi < 4; mi++)
        #pragma unroll
        for (int ni = 0; ni < 8; ni++)
            #pragma unroll
            for (int j = 0; j < 4; j++) acc[mi][ni][j] = 0.f;

    // prologue: stages 0, 1 in flight
    prefetch_stage(sb, 0, A, Bt, rowA0, colB0, Ktot, 0, tid);
    asm volatile("cp.async.commit_group;" ::: "memory");
    prefetch_stage(sb, 1, A, Bt, rowA0, colB0, Ktot, TKH, tid);
    asm volatile("cp.async.commit_group;" ::: "memory");

    const int lr = lane >> 2;   // 0..7
    const int lc = lane & 3;    // 0..3

    int buf = 0;                // = s % 3
    for (int s = 0; s < NS; s++) {
        asm volatile("cp.async.wait_group 1;" ::: "memory");
        __syncthreads();        // stage s ready; buffer (s+2)%3 free since iter s-1

        if (s + 2 < NS) {
            int nbuf = buf + 2; if (nbuf >= NSTAGE) nbuf -= NSTAGE;
            prefetch_stage(sb, nbuf, A, Bt, rowA0, colB0, Ktot, (s + 2) * TKH, tid);
        }
        asm volatile("cp.async.commit_group;" ::: "memory");

        const __half* sA = (const __half*)(smem + buf * STAGE_BYTES);
        const __half* sB = (const __half*)(smem + buf * STAGE_BYTES + A_BYTES);

        #pragma unroll
        for (int ks = 0; ks < 4; ks++) {            // 4 x k16 = TKH
            int kb = ks * 16;                       // half index within row
            uint32_t afr[4][4];
            uint32_t bfr[8][2];
            #pragma unroll
            for (int mi = 0; mi < 4; mi++) {
                int r = wm * 64 + mi * 16 + lr;
                int c = kb + 2 * lc;
                afr[mi][0] = *(const uint32_t*)(sA + r * SROWH + c);
                afr[mi][1] = *(const uint32_t*)(sA + (r + 8) * SROWH + c);
                afr[mi][2] = *(const uint32_t*)(sA + r * SROWH + c + 8);
                afr[mi][3] = *(const uint32_t*)(sA + (r + 8) * SROWH + c + 8);
            }
            #pragma unroll
            for (int ni = 0; ni < 8; ni++) {
                int n = wn * 64 + ni * 8 + lr;
                int c = kb + 2 * lc;
                bfr[ni][0] = *(const uint32_t*)(sB + n * SROWH + c);
                bfr[ni][1] = *(const uint32_t*)(sB + n * SROWH + c + 8);
            }
            #pragma unroll
            for (int mi = 0; mi < 4; mi++)
                #pragma unroll
                for (int ni = 0; ni < 8; ni++)
                    mma16816(acc[mi][ni], afr[mi], bfr[ni]);
        }

        buf++; if (buf >= NSTAGE) buf -= NSTAGE;
    }

    // ------------------------- epilogue -------------------------
    // accum layout m16n8: c0/c1 at (row lr, col 2*lc / 2*lc+1), c2/c3 at row lr+8
    #pragma unroll
    for (int mi = 0; mi < 4; mi++) {
        size_t m0 = rowA0 + (size_t)(wm * 64 + mi * 16 + lr);
        size_t m1 = m0 + 8;
        if (mode == 0) {
            __half* row0 = g_h + m0 * (size_t)Ntot;
            __half* row1 = g_h + m1 * (size_t)Ntot;
            #pragma unroll
            for (int ni = 0; ni < 8; ni++) {
                size_t col = colB0 + wn * 64 + ni * 8 + lc * 2;
                float b0 = bias[col], b1 = bias[col + 1];
                *(__half2*)(row0 + col) = __floats2half2_rn(
                    gelu_tanh(acc[mi][ni][0] + b0), gelu_tanh(acc[mi][ni][1] + b1));
                *(__half2*)(row1 + col) = __floats2half2_rn(
                    gelu_tanh(acc[mi][ni][2] + b0), gelu_tanh(acc[mi][ni][3] + b1));
            }
        } else {
            int tok0 = g_idx[m0], tok1 = g_idx[m1];
            int b0i = (int)(m0 >> 11), b1i = (int)(m1 >> 11);
            float* row0 = out + ((size_t)(b0i * L_ + tok0)) * D_;
            float* row1 = out + ((size_t)(b1i * L_ + tok1)) * D_;
            #pragma unroll
            for (int ni = 0; ni < 8; ni++) {
                size_t col = colB0 + wn * 64 + ni * 8 + lc * 2;
                float b0 = bias[col], b1 = bias[col + 1];
                float2 v0, v1;
                v0.x = acc[mi][ni][0] + b0;
                v0.y = acc[mi][ni][1] + b1;
                v1.x = acc[mi][ni][2] + b0;
                v1.y = acc[mi][ni][3] + b1;
                *(float2*)(row0 + col) = v0;
                *(float2*)(row1 + col) = v1;
            }
        }
    }
}

// ---------------------------------------------------------------------------
// Host entry.
// Launch order: router(0) topksel(1) prep(2) GEMM1(3=profiled) zero(4) gemm2(5)
// ---------------------------------------------------------------------------
extern "C" void kernel_launch(void* const* d_in, const int* in_sizes, int n_in,
                              void* d_out, int out_size) {
    (void)in_sizes; (void)n_in;
    const float* x  = (const float*)d_in[0];
    const float* wr = (const float*)d_in[1];
    const float* br = (const float*)d_in[2];
    const float* w1 = (const float*)d_in[3];
    const float* b1 = (const float*)d_in[4];
    const float* w2 = (const float*)d_in[5];
    const float* b2 = (const float*)d_in[6];
    float* out = (float*)d_out;

    static int smem_set = 0;
    if (!smem_set) {
        cudaFuncSetAttribute(k_gemm, cudaFuncAttributeMaxDynamicSharedMemorySize, SM_TOTAL);
        smem_set = 1;
    }

    // 0) router scores (fp32 exact)
    k_router<<<(B_ * L_ * 32) / 256, 256>>>(x, wr, br);

    // 1) threshold + index build (fused)
    k_topksel<<<B_, 1024>>>();

    // 2) gather -> fp16  +  both weight transposes -> fp16 K-major (one launch)
    k_prep<<<NB_PREP, 256>>>(x, w1, w2);

    // 3) GEMM1 (profiled slot)
    k_gemm<<<dim3(DF_ / 128, BK / 128), 128, SM_TOTAL>>>(b1, out, D_,  DF_, 0);

    // 4) zero output (gemm1 never touches out; completes before gemm2 scatter)
    k_zero<<<2048, 256>>>((float4*)out, (size_t)out_size / 4);

    // 5) GEMM2 (scatter epilogue)
    k_gemm<<<dim3(D_ / 128, BK / 128), 128, SM_TOTAL>>>(b2, out, DF_, D_, 1);
}